// round 1
// baseline (speedup 1.0000x reference)
#include <cuda_runtime.h>
#include <cuda_bf16.h>

// Problem constants
#define BATCH    16384
#define FEAT     512
#define NODES    4095      // 2^12 - 1
#define PSTRIDE  4096      // padded row stride for P
#define TDEPTH   12
#define LEAVES   4096

// GEMM tiling
#define BM 128
#define BN 128
#define BK 8

// 256 MiB scratch for node probabilities P[BATCH][PSTRIDE]
__device__ float g_P[(size_t)BATCH * PSTRIDE];

__device__ __forceinline__ float fast_sigmoid(float x) {
    return 1.0f / (1.0f + __expf(-x));
}

// ---------------------------------------------------------------------------
// Kernel 1: P[m][n] = sigmoid( (x[m,:] . W[n,:] + b[n]) * s[n] )
// Block computes a 128x128 tile of P. 256 threads, 8x8 per thread (4+4 split).
// ---------------------------------------------------------------------------
__global__ __launch_bounds__(256, 2)
void gemm_sig(const float* __restrict__ X, const float* __restrict__ W,
              const float* __restrict__ bias, const float* __restrict__ scale)
{
    __shared__ float As[BK][BM];
    __shared__ float Bs[BK][BN];

    const int tid = threadIdx.x;
    const int m0  = blockIdx.y * BM;
    const int n0  = blockIdx.x * BN;

    // Global->smem loader mapping: each thread loads one float4 from A and B
    const int lrow = tid >> 1;          // 0..127
    const int lk   = (tid & 1) * 4;     // 0 or 4

    const float* gA = X + (size_t)(m0 + lrow) * FEAT + lk;
    const float* gB = W + (size_t)(n0 + lrow) * FEAT + lk;
    const bool bvalid = (n0 + lrow) < NODES;

    float4 ra = *(const float4*)gA;
    float4 rb = bvalid ? *(const float4*)gB : make_float4(0.f, 0.f, 0.f, 0.f);

    // Compute mapping (split tiles to reduce smem conflicts)
    const int ry = (tid >> 4) * 4;      // 0..60
    const int cx = (tid & 15) * 4;      // 0..60

    float acc[8][8];
    #pragma unroll
    for (int i = 0; i < 8; i++)
        #pragma unroll
        for (int j = 0; j < 8; j++)
            acc[i][j] = 0.f;

    const int KT = FEAT / BK;           // 64
    for (int kt = 0; kt < KT; ++kt) {
        // regs -> smem (transposed to k-major)
        As[lk + 0][lrow] = ra.x;
        As[lk + 1][lrow] = ra.y;
        As[lk + 2][lrow] = ra.z;
        As[lk + 3][lrow] = ra.w;
        Bs[lk + 0][lrow] = rb.x;
        Bs[lk + 1][lrow] = rb.y;
        Bs[lk + 2][lrow] = rb.z;
        Bs[lk + 3][lrow] = rb.w;
        __syncthreads();

        // prefetch next k-tile while computing this one
        if (kt + 1 < KT) {
            ra = *(const float4*)(gA + (kt + 1) * BK);
            rb = bvalid ? *(const float4*)(gB + (kt + 1) * BK)
                        : make_float4(0.f, 0.f, 0.f, 0.f);
        }

        #pragma unroll
        for (int k = 0; k < BK; k++) {
            float4 a0 = *(const float4*)&As[k][ry];
            float4 a1 = *(const float4*)&As[k][ry + 64];
            float4 b0 = *(const float4*)&Bs[k][cx];
            float4 b1 = *(const float4*)&Bs[k][cx + 64];
            float av[8] = {a0.x, a0.y, a0.z, a0.w, a1.x, a1.y, a1.z, a1.w};
            float bv[8] = {b0.x, b0.y, b0.z, b0.w, b1.x, b1.y, b1.z, b1.w};
            #pragma unroll
            for (int i = 0; i < 8; i++)
                #pragma unroll
                for (int j = 0; j < 8; j++)
                    acc[i][j] = __fmaf_rn(av[i], bv[j], acc[i][j]);
        }
        __syncthreads();
    }

    // Epilogue: bias, scale, sigmoid, store P
    const bool tail = (n0 + BN > NODES);   // only last column-block
    #pragma unroll
    for (int i = 0; i < 8; i++) {
        const int gm = m0 + ry + ((i < 4) ? i : (64 + i - 4));
        float* prow = g_P + (size_t)gm * PSTRIDE;
        if (!tail) {
            // two vectorized stores per row
            float4 v0, v1;
            {
                int n = n0 + cx;
                v0.x = fast_sigmoid((acc[i][0] + bias[n + 0]) * scale[n + 0]);
                v0.y = fast_sigmoid((acc[i][1] + bias[n + 1]) * scale[n + 1]);
                v0.z = fast_sigmoid((acc[i][2] + bias[n + 2]) * scale[n + 2]);
                v0.w = fast_sigmoid((acc[i][3] + bias[n + 3]) * scale[n + 3]);
                *(float4*)&prow[n] = v0;
            }
            {
                int n = n0 + cx + 64;
                v1.x = fast_sigmoid((acc[i][4] + bias[n + 0]) * scale[n + 0]);
                v1.y = fast_sigmoid((acc[i][5] + bias[n + 1]) * scale[n + 1]);
                v1.z = fast_sigmoid((acc[i][6] + bias[n + 2]) * scale[n + 2]);
                v1.w = fast_sigmoid((acc[i][7] + bias[n + 3]) * scale[n + 3]);
                *(float4*)&prow[n] = v1;
            }
        } else {
            #pragma unroll
            for (int j = 0; j < 8; j++) {
                const int gn = n0 + cx + ((j < 4) ? j : (64 + j - 4));
                if (gn < NODES) {
                    float p = fast_sigmoid((acc[i][j] + bias[gn]) * scale[gn]);
                    prow[gn] = p;
                }
            }
        }
    }
}

// ---------------------------------------------------------------------------
// Kernel 2: per-row tree expansion + leaf-weighted sum.
// One block per batch row. P row (16KB) staged in smem; ping-pong expansion.
// ---------------------------------------------------------------------------
__global__ __launch_bounds__(256)
void tree_kernel(const float* __restrict__ leaves, float* __restrict__ out)
{
    __shared__ float pRow[PSTRIDE];
    __shared__ float bufA[LEAVES];
    __shared__ float bufB[LEAVES];

    const int row = blockIdx.x;
    const int tid = threadIdx.x;
    const float* Pr = g_P + (size_t)row * PSTRIDE;

    // bulk load the full P row (vectorized, coalesced)
    #pragma unroll
    for (int i = tid; i < PSTRIDE / 4; i += 256)
        ((float4*)pRow)[i] = ((const float4*)Pr)[i];
    if (tid == 0) bufA[0] = 1.0f;
    __syncthreads();

    float* cur = bufA;
    float* nxt = bufB;
    #pragma unroll
    for (int d = 0; d < TDEPTH; d++) {
        const int cnt = 1 << d;
        const int st  = cnt - 1;
        for (int i = tid; i < cnt; i += 256) {
            float p = pRow[st + i];
            float o = cur[i];
            nxt[2 * i]     = o * p;
            nxt[2 * i + 1] = __fmaf_rn(-o, p, o);   // o * (1 - p)
        }
        __syncthreads();
        float* t = cur; cur = nxt; nxt = t;
    }

    // sum over leaves: sigmoid(leaves[l]) * leafprob[l]
    float acc = 0.f;
    for (int l = tid; l < LEAVES; l += 256)
        acc = __fmaf_rn(fast_sigmoid(leaves[l]), cur[l], acc);

    #pragma unroll
    for (int o = 16; o; o >>= 1)
        acc += __shfl_xor_sync(0xffffffffu, acc, o);
    if ((tid & 31) == 0) nxt[tid >> 5] = acc;
    __syncthreads();
    if (tid < 8) {
        float v = nxt[tid];
        #pragma unroll
        for (int o = 4; o; o >>= 1)
            v += __shfl_xor_sync(0xffu, v, o);
        if (tid == 0) out[row] = v;
    }
}

// ---------------------------------------------------------------------------
extern "C" void kernel_launch(void* const* d_in, const int* in_sizes, int n_in,
                              void* d_out, int out_size)
{
    const float* X      = (const float*)d_in[0];  // [16384, 512]
    const float* W      = (const float*)d_in[1];  // [4095, 512]
    const float* b      = (const float*)d_in[2];  // [4095]
    const float* s      = (const float*)d_in[3];  // [4095]
    const float* leaves = (const float*)d_in[4];  // [4096]
    float* out = (float*)d_out;                   // [16384]

    dim3 g1((NODES + BN - 1) / BN, BATCH / BM);   // 32 x 128
    gemm_sig<<<g1, 256>>>(X, W, b, s);
    tree_kernel<<<BATCH, 256>>>(leaves, out);
}

// round 3
// speedup vs baseline: 1.8475x; 1.8475x over previous
#include <cuda_runtime.h>
#include <cstdint>

#define BATCH   16384
#define FEAT    512
#define NODES   4095
#define NPAD    4096

// GEMM tile
#define BM 128
#define BN 128
#define BK 16            // two k8 sub-steps per stage
#define NSTAGE (FEAT / BK)   // 32

// P transposed: P_T[node][batch]
__device__ float g_P[(size_t)NPAD * BATCH];

__device__ __forceinline__ float fast_sigmoid(float x) {
    return 1.0f / (1.0f + __expf(-x));
}
__device__ __forceinline__ uint32_t to_tf32(float v) {
    uint32_t o;
    asm("cvt.rna.tf32.f32 %0, %1;" : "=r"(o) : "f"(v));
    return o;
}
__device__ __forceinline__ void mma_tf32(float* c, const uint32_t* a, const uint32_t* b) {
    asm volatile(
        "mma.sync.aligned.m16n8k8.row.col.f32.tf32.tf32.f32 "
        "{%0,%1,%2,%3}, {%4,%5,%6,%7}, {%8,%9}, {%0,%1,%2,%3};"
        : "+f"(c[0]), "+f"(c[1]), "+f"(c[2]), "+f"(c[3])
        : "r"(a[0]), "r"(a[1]), "r"(a[2]), "r"(a[3]), "r"(b[0]), "r"(b[1]));
}

// ---------------------------------------------------------------------------
// Kernel 1: tf32 mma.sync GEMM + sigmoid epilogue -> P_T[node][batch]
//
// Fragment-ready smem: A stored as [k8s][m16tile][lane][4] so one lds.128
// yields a thread's whole A fragment; B as [k8s][n8tile][lane][2] (lds.64).
// ---------------------------------------------------------------------------
__global__ __launch_bounds__(256, 2)
void gemm_mma(const float* __restrict__ X, const float* __restrict__ W,
              const float* __restrict__ bias, const float* __restrict__ scale)
{
    // per stage: A 2*8*32*4 = 2048 u32 (8KB), B 2*16*32*2 = 2048 u32 (8KB)
    __shared__ uint32_t sA[2][2048];
    __shared__ uint32_t sB[2][2048];
    __shared__ float sbias[BN], sscale[BN];

    const int tid  = threadIdx.x;
    const int lane = tid & 31;
    const int wid  = tid >> 5;
    const int warpM = wid & 1;       // 2 x 64 rows
    const int warpN = wid >> 1;      // 4 x 32 cols
    const int m0 = blockIdx.y * BM;
    const int n0 = blockIdx.x * BN;

    // loader mapping: two slices of [0,512) per thread for A and for B
    // i -> row = i>>2, k4 = i&3 (4 k-contig floats)
    const int iA0 = tid, iA1 = tid + 256;

    {
        int n = n0 + tid >= NODES ? 0 : n0 + tid;   // pad col -> harmless
        if (tid < BN) {
            int nn = n0 + tid;
            bool v = nn < NODES;
            sbias[tid]  = v ? bias[nn] : 0.f;
            sscale[tid] = v ? scale[nn] : 1.f;
        }
        (void)n;
    }

    float acc[4][4][4];
    #pragma unroll
    for (int f = 0; f < 4; f++)
        #pragma unroll
        for (int g = 0; g < 4; g++)
            #pragma unroll
            for (int j = 0; j < 4; j++)
                acc[f][g][j] = 0.f;

    // ---- staging helpers (computed constants per loader slice) ----
    auto stageA = [&](int buf, int i, float4 v) {
        const int m = i >> 2, k4 = i & 3;
        const int k8s = k4 >> 1;
        const int m16t = m >> 4, r = m & 15;
        const int slot = (r >> 3) + ((k4 & 1) ? 2 : 0);
        uint32_t* p = &sA[buf][((k8s * 8 + m16t) * 32 + (r & 7) * 4) * 4 + slot];
        p[0]  = to_tf32(v.x);
        p[4]  = to_tf32(v.y);
        p[8]  = to_tf32(v.z);
        p[12] = to_tf32(v.w);
    };
    auto stageB = [&](int buf, int i, float4 v) {
        const int n = i >> 2, k4 = i & 3;
        const int k8s = k4 >> 1;
        const int n8t = n >> 3, rn = n & 7;
        const int slot = (k4 & 1);
        uint32_t* p = &sB[buf][((k8s * 16 + n8t) * 32 + rn * 4) * 2 + slot];
        p[0] = to_tf32(v.x);
        p[2] = to_tf32(v.y);
        p[4] = to_tf32(v.z);
        p[6] = to_tf32(v.w);
    };
    auto loadA = [&](int i, int ks) -> float4 {
        const int m = i >> 2, k4 = i & 3;
        return *(const float4*)(X + (size_t)(m0 + m) * FEAT + ks + k4 * 4);
    };
    auto loadB = [&](int i, int ks) -> float4 {
        const int n = i >> 2, k4 = i & 3;
        int nn = n0 + n; if (nn >= NODES) nn = 0;    // pad row, never read
        return *(const float4*)(W + (size_t)nn * FEAT + ks + k4 * 4);
    };

    // prologue: stage 0
    float4 ra0 = loadA(iA0, 0), ra1 = loadA(iA1, 0);
    float4 rb0 = loadB(iA0, 0), rb1 = loadB(iA1, 0);

    for (int kt = 0; kt < NSTAGE; ++kt) {
        const int buf = kt & 1;
        stageA(buf, iA0, ra0); stageA(buf, iA1, ra1);
        stageB(buf, iA0, rb0); stageB(buf, iA1, rb1);
        __syncthreads();

        if (kt + 1 < NSTAGE) {
            const int ks = (kt + 1) * BK;
            ra0 = loadA(iA0, ks); ra1 = loadA(iA1, ks);
            rb0 = loadB(iA0, ks); rb1 = loadB(iA1, ks);
        }

        #pragma unroll
        for (int k8s = 0; k8s < 2; ++k8s) {
            uint32_t af[4][4];
            uint32_t bf[4][2];
            #pragma unroll
            for (int f = 0; f < 4; ++f) {
                uint4 t = *(const uint4*)&sA[buf][((k8s * 8 + warpM * 4 + f) * 32 + lane) * 4];
                af[f][0] = t.x; af[f][1] = t.y; af[f][2] = t.z; af[f][3] = t.w;
            }
            #pragma unroll
            for (int g = 0; g < 4; ++g) {
                uint2 t = *(const uint2*)&sB[buf][((k8s * 16 + warpN * 4 + g) * 32 + lane) * 2];
                bf[g][0] = t.x; bf[g][1] = t.y;
            }
            #pragma unroll
            for (int f = 0; f < 4; ++f)
                #pragma unroll
                for (int g = 0; g < 4; ++g)
                    mma_tf32(acc[f][g], af[f], bf[g]);
        }
        __syncthreads();
    }

    // Epilogue: c-frag (m16n8): rows lane>>2 (+8), cols (lane&3)*2 (+1)
    const int rbase = m0 + warpM * 64 + (lane >> 2);
    #pragma unroll
    for (int f = 0; f < 4; ++f) {
        #pragma unroll
        for (int g = 0; g < 4; ++g) {
            const int cidx = warpN * 32 + g * 8 + (lane & 3) * 2;
            const int m = rbase + f * 16;
            #pragma unroll
            for (int j = 0; j < 4; ++j) {
                const int col = cidx + (j & 1);
                const int mm  = m + ((j >> 1) ? 8 : 0);
                float p = fast_sigmoid((acc[f][g][j] + sbias[col]) * sscale[col]);
                g_P[(size_t)(n0 + col) * BATCH + mm] = p;
            }
        }
    }
}

// ---------------------------------------------------------------------------
// Kernel 2: leaf-group tree walk on P_T. Thread = (row, segment of 64 groups).
// ---------------------------------------------------------------------------
__global__ __launch_bounds__(256)
void tree_kernel(const float* __restrict__ leaves, float* __restrict__ out)
{
    __shared__ float sl[4096];
    __shared__ float part[8][33];
    const int tid = threadIdx.x;

    for (int i = tid; i < 4096; i += 256)
        sl[i] = fast_sigmoid(leaves[i]);
    __syncthreads();

    const int rlane = tid & 31;
    const int seg   = tid >> 5;
    const int r     = blockIdx.x * 32 + rlane;
    const float* __restrict__ PT = g_P;

    float acc = 0.f;
    const int g0 = seg * 64;
    for (int gi = 0; gi < 64; ++gi) {
        const int g = g0 + gi;
        float pref = 1.f;
        #pragma unroll
        for (int d = 0; d < 9; ++d) {
            int idx = (1 << d) - 1 + (g >> (9 - d));
            float p = PT[(size_t)idx * BATCH + r];
            int b = (g >> (8 - d)) & 1;
            pref = b ? (pref - pref * p) : (pref * p);
        }
        float p9  = PT[(size_t)(511  + g)     * BATCH + r];
        float pa0 = PT[(size_t)(1023 + 2 * g) * BATCH + r];
        float pa1 = PT[(size_t)(1024 + 2 * g) * BATCH + r];
        float pb0 = PT[(size_t)(2047 + 4 * g) * BATCH + r];
        float pb1 = PT[(size_t)(2048 + 4 * g) * BATCH + r];
        float pb2 = PT[(size_t)(2049 + 4 * g) * BATCH + r];
        float pb3 = PT[(size_t)(2050 + 4 * g) * BATCH + r];

        float u0 = pref * p9,  u1 = pref - u0;
        float v0 = u0 * pa0,   v1 = u0 - v0;
        float v2 = u1 * pa1,   v3 = u1 - v2;
        float w0 = v0 * pb0,   w1 = v0 - w0;
        float w2 = v1 * pb1,   w3 = v1 - w2;
        float w4 = v2 * pb2,   w5 = v2 - w4;
        float w6 = v3 * pb3,   w7 = v3 - w6;

        const float* s8 = &sl[g * 8];
        acc += s8[0] * w0 + s8[1] * w1 + s8[2] * w2 + s8[3] * w3
             + s8[4] * w4 + s8[5] * w5 + s8[6] * w6 + s8[7] * w7;
    }
    part[seg][rlane] = acc;
    __syncthreads();
    if (tid < 32) {
        float t = 0.f;
        #pragma unroll
        for (int s2 = 0; s2 < 8; ++s2) t += part[s2][tid];
        out[blockIdx.x * 32 + tid] = t;
    }
}

// ---------------------------------------------------------------------------
extern "C" void kernel_launch(void* const* d_in, const int* in_sizes, int n_in,
                              void* d_out, int out_size)
{
    const float* X      = (const float*)d_in[0];  // [16384, 512]
    const float* W      = (const float*)d_in[1];  // [4095, 512]
    const float* b      = (const float*)d_in[2];  // [4095]
    const float* s      = (const float*)d_in[3];  // [4095]
    const float* leaves = (const float*)d_in[4];  // [4096]
    float* out = (float*)d_out;                   // [16384]

    dim3 g1(NPAD / BN, BATCH / BM);               // (32, 128)
    gemm_mma<<<g1, 256>>>(X, W, b, s);
    tree_kernel<<<512, 256>>>(leaves, out);
}

// round 4
// speedup vs baseline: 5.5698x; 3.0148x over previous
#include <cuda_runtime.h>
#include <cuda_fp16.h>
#include <cstdint>

#define BATCH   16384
#define FEAT    512
#define NODES   4095
#define NPAD    4096

#define BM 128
#define BN 128
#define BKH 64                 // halves per k-stage (128B rows)
#define NKSTAGE (FEAT / BKH)   // 8
#define PSTAGES 3              // cp.async pipeline depth

// smem: A stages [0,48K), B stages [48K,96K), bias 96K, scale 96K+512
#define SMA(s)   ((s) * 16384)
#define SMB(s)   (49152 + (s) * 16384)
#define SM_BIAS  98304
#define SM_SCALE 98816
#define SM_TOTAL 99328

__device__ float g_P[(size_t)NPAD * BATCH];          // P_T[node][batch]
__device__ __half g_Xh[(size_t)BATCH * FEAT];
__device__ __half g_Wh[(size_t)NPAD * FEAT];         // row 4095 zeroed

__device__ __forceinline__ float fast_sigmoid(float x) {
    return 1.0f / (1.0f + __expf(-x));
}
__device__ __forceinline__ uint32_t smem_u32(const void* p) {
    return (uint32_t)__cvta_generic_to_shared(p);
}
__device__ __forceinline__ void cp16(uint32_t dst, const void* src) {
    asm volatile("cp.async.cg.shared.global [%0], [%1], 16;" :: "r"(dst), "l"(src));
}
__device__ __forceinline__ void cp_commit() {
    asm volatile("cp.async.commit_group;" ::: "memory");
}
__device__ __forceinline__ void cp_wait1() {
    asm volatile("cp.async.wait_group 1;" ::: "memory");
}
__device__ __forceinline__ void ldsm4(uint32_t& r0, uint32_t& r1, uint32_t& r2,
                                      uint32_t& r3, uint32_t a) {
    asm volatile("ldmatrix.sync.aligned.m8n8.x4.shared.b16 {%0,%1,%2,%3}, [%4];"
                 : "=r"(r0), "=r"(r1), "=r"(r2), "=r"(r3) : "r"(a));
}
__device__ __forceinline__ void mma_f16(float* c, const uint32_t* a, const uint32_t* b) {
    asm volatile(
        "mma.sync.aligned.m16n8k16.row.col.f32.f16.f16.f32 "
        "{%0,%1,%2,%3}, {%4,%5,%6,%7}, {%8,%9}, {%0,%1,%2,%3};"
        : "+f"(c[0]), "+f"(c[1]), "+f"(c[2]), "+f"(c[3])
        : "r"(a[0]), "r"(a[1]), "r"(a[2]), "r"(a[3]), "r"(b[0]), "r"(b[1]));
}

// ---------------------------------------------------------------------------
// Convert kernels: fp32 -> fp16 copies of X and W (W padded to 4096 rows)
// ---------------------------------------------------------------------------
__global__ __launch_bounds__(256)
void convX(const float* __restrict__ X)
{
    size_t i = (size_t)blockIdx.x * 256 + threadIdx.x;   // float4 index
    float4 v = ((const float4*)X)[i];
    __half2* d = (__half2*)g_Xh;
    d[2 * i]     = __floats2half2_rn(v.x, v.y);
    d[2 * i + 1] = __floats2half2_rn(v.z, v.w);
}
__global__ __launch_bounds__(256)
void convW(const float* __restrict__ W)
{
    size_t i = (size_t)blockIdx.x * 256 + threadIdx.x;   // float4 index, 524288 total
    __half2* d = (__half2*)g_Wh;
    if (i < (size_t)NODES * FEAT / 4) {
        float4 v = ((const float4*)W)[i];
        d[2 * i]     = __floats2half2_rn(v.x, v.y);
        d[2 * i + 1] = __floats2half2_rn(v.z, v.w);
    } else {
        d[2 * i]     = __floats2half2_rn(0.f, 0.f);
        d[2 * i + 1] = __floats2half2_rn(0.f, 0.f);
    }
}

// ---------------------------------------------------------------------------
// Kernel 1: fp16 mma.sync GEMM (cp.async + ldmatrix) -> P_T[node][batch]
// ---------------------------------------------------------------------------
__global__ __launch_bounds__(256, 2)
void gemm_mma(const float* __restrict__ bias, const float* __restrict__ scale)
{
    extern __shared__ char smem[];
    const uint32_t sbase = smem_u32(smem);

    const int tid  = threadIdx.x;
    const int lane = tid & 31;
    const int wid  = tid >> 5;
    const int warpM = wid & 1;          // 2 x 64 rows
    const int warpN = wid >> 1;         // 4 x 32 cols
    const int m0 = blockIdx.y * BM;
    const int n0 = blockIdx.x * BN;

    float* sb = (float*)(smem + SM_BIAS);
    float* ss = (float*)(smem + SM_SCALE);
    if (tid < BN) {
        int nn = n0 + tid;
        bool v = nn < NODES;
        sb[tid] = v ? bias[nn] : 0.f;
        ss[tid] = v ? scale[nn] : 1.f;
    }

    // cp.async stage loader: 4 A-chunks + 4 B-chunks of 16B per thread
    auto issue_stage = [&](int kt) {
        const int s = kt % PSTAGES;
        const int kb = kt * BKH;                       // k offset in halves
        #pragma unroll
        for (int i = 0; i < 4; ++i) {
            int c = tid + i * 256;                     // 0..1023
            int row = c >> 3, chk = c & 7;
            uint32_t coff = (uint32_t)(chk * 16) ^ ((row & 7) << 4);
            cp16(sbase + SMA(s) + row * 128 + coff,
                 g_Xh + (size_t)(m0 + row) * FEAT + kb + chk * 8);
        }
        #pragma unroll
        for (int i = 0; i < 4; ++i) {
            int c = tid + i * 256;
            int row = c >> 3, chk = c & 7;
            uint32_t coff = (uint32_t)(chk * 16) ^ ((row & 7) << 4);
            cp16(sbase + SMB(s) + row * 128 + coff,
                 g_Wh + (size_t)(n0 + row) * FEAT + kb + chk * 8);
        }
        cp_commit();
    };

    float acc[4][4][4];
    #pragma unroll
    for (int f = 0; f < 4; f++)
        #pragma unroll
        for (int g = 0; g < 4; g++)
            #pragma unroll
            for (int j = 0; j < 4; j++)
                acc[f][g][j] = 0.f;

    issue_stage(0);
    issue_stage(1);

    const int q  = lane >> 3;           // 0..3
    const int lr = lane & 7;            // 0..7

    for (int kt = 0; kt < NKSTAGE; ++kt) {
        cp_wait1();
        __syncthreads();
        if (kt + 2 < NKSTAGE) issue_stage(kt + 2);
        else cp_commit();               // keep group arithmetic exact

        const uint32_t abase = sbase + SMA(kt % PSTAGES);
        const uint32_t bbase = sbase + SMB(kt % PSTAGES);

        #pragma unroll
        for (int g = 0; g < 4; ++g) {   // k16 groups within BK=64
            // A frags: 4 m16 tiles
            uint32_t af[4][4];
            #pragma unroll
            for (int t = 0; t < 4; ++t) {
                int trow = warpM * 64 + t * 16 + lr + (q & 1) * 8;
                uint32_t kbyte = (uint32_t)(g * 32 + (q >> 1) * 16);
                uint32_t addr = abase + trow * 128 + (kbyte ^ ((trow & 7) << 4));
                ldsm4(af[t][0], af[t][1], af[t][2], af[t][3], addr);
            }
            // B frags: 2 n16 tiles -> 4 n8 frags
            uint32_t bf[2][4];
            #pragma unroll
            for (int t = 0; t < 2; ++t) {
                int nrow = warpN * 32 + t * 16 + lr + (q >> 1) * 8;
                uint32_t kbyte = (uint32_t)(g * 32 + (q & 1) * 16);
                uint32_t addr = bbase + nrow * 128 + (kbyte ^ ((nrow & 7) << 4));
                ldsm4(bf[t][0], bf[t][1], bf[t][2], bf[t][3], addr);
            }
            #pragma unroll
            for (int f = 0; f < 4; ++f)
                #pragma unroll
                for (int gg = 0; gg < 4; ++gg) {
                    uint32_t bb[2] = { bf[gg >> 1][(gg & 1) * 2],
                                       bf[gg >> 1][(gg & 1) * 2 + 1] };
                    mma_f16(acc[f][gg], af[f], bb);
                }
        }
        __syncthreads();
    }

    // Epilogue: C frag m16n8 -> P_T[node][batch]
    const int rbase = m0 + warpM * 64 + (lane >> 2);
    #pragma unroll
    for (int f = 0; f < 4; ++f) {
        #pragma unroll
        for (int g = 0; g < 4; ++g) {
            const int cidx = warpN * 32 + g * 8 + (lane & 3) * 2;
            const int m = rbase + f * 16;
            #pragma unroll
            for (int j = 0; j < 4; ++j) {
                const int col = cidx + (j & 1);
                const int mm  = m + ((j >> 1) ? 8 : 0);
                float p = fast_sigmoid((acc[f][g][j] + sb[col]) * ss[col]);
                g_P[(size_t)(n0 + col) * BATCH + mm] = p;
            }
        }
    }
}

// ---------------------------------------------------------------------------
// Kernel 2: leaf-group tree walk on P_T. Thread = (row, segment of 64 groups).
// ---------------------------------------------------------------------------
__global__ __launch_bounds__(256)
void tree_kernel(const float* __restrict__ leaves, float* __restrict__ out)
{
    __shared__ float sl[4096];
    __shared__ float part[8][33];
    const int tid = threadIdx.x;

    for (int i = tid; i < 4096; i += 256)
        sl[i] = fast_sigmoid(leaves[i]);
    __syncthreads();

    const int rlane = tid & 31;
    const int seg   = tid >> 5;
    const int r     = blockIdx.x * 32 + rlane;
    const float* __restrict__ PT = g_P;

    float acc = 0.f;
    const int g0 = seg * 64;
    for (int gi = 0; gi < 64; ++gi) {
        const int g = g0 + gi;
        float pref = 1.f;
        #pragma unroll
        for (int d = 0; d < 9; ++d) {
            int idx = (1 << d) - 1 + (g >> (9 - d));
            float p = PT[(size_t)idx * BATCH + r];
            int b = (g >> (8 - d)) & 1;
            pref = b ? (pref - pref * p) : (pref * p);
        }
        float p9  = PT[(size_t)(511  + g)     * BATCH + r];
        float pa0 = PT[(size_t)(1023 + 2 * g) * BATCH + r];
        float pa1 = PT[(size_t)(1024 + 2 * g) * BATCH + r];
        float pb0 = PT[(size_t)(2047 + 4 * g) * BATCH + r];
        float pb1 = PT[(size_t)(2048 + 4 * g) * BATCH + r];
        float pb2 = PT[(size_t)(2049 + 4 * g) * BATCH + r];
        float pb3 = PT[(size_t)(2050 + 4 * g) * BATCH + r];

        float u0 = pref * p9,  u1 = pref - u0;
        float v0 = u0 * pa0,   v1 = u0 - v0;
        float v2 = u1 * pa1,   v3 = u1 - v2;
        float w0 = v0 * pb0,   w1 = v0 - w0;
        float w2 = v1 * pb1,   w3 = v1 - w2;
        float w4 = v2 * pb2,   w5 = v2 - w4;
        float w6 = v3 * pb3,   w7 = v3 - w6;

        const float* s8 = &sl[g * 8];
        acc += s8[0] * w0 + s8[1] * w1 + s8[2] * w2 + s8[3] * w3
             + s8[4] * w4 + s8[5] * w5 + s8[6] * w6 + s8[7] * w7;
    }
    part[seg][rlane] = acc;
    __syncthreads();
    if (tid < 32) {
        float t = 0.f;
        #pragma unroll
        for (int s2 = 0; s2 < 8; ++s2) t += part[s2][tid];
        out[blockIdx.x * 32 + tid] = t;
    }
}

// ---------------------------------------------------------------------------
extern "C" void kernel_launch(void* const* d_in, const int* in_sizes, int n_in,
                              void* d_out, int out_size)
{
    const float* X      = (const float*)d_in[0];  // [16384, 512]
    const float* W      = (const float*)d_in[1];  // [4095, 512]
    const float* b      = (const float*)d_in[2];  // [4095]
    const float* s      = (const float*)d_in[3];  // [4095]
    const float* leaves = (const float*)d_in[4];  // [4096]
    float* out = (float*)d_out;                   // [16384]

    static bool attr_set = false;
    if (!attr_set) {
        cudaFuncSetAttribute(gemm_mma, cudaFuncAttributeMaxDynamicSharedMemorySize,
                             SM_TOTAL);
        attr_set = true;
    }

    convX<<<BATCH * FEAT / 4 / 256, 256>>>(X);            // 8192 blocks
    convW<<<NPAD * FEAT / 4 / 256, 256>>>(W);             // 2048 blocks
    dim3 g1(NPAD / BN, BATCH / BM);                       // (32, 128)
    gemm_mma<<<g1, 256, SM_TOTAL>>>(b, s);
    tree_kernel<<<512, 256>>>(leaves, out);
}

// round 5
// speedup vs baseline: 5.6927x; 1.0221x over previous
#include <cuda_runtime.h>
#include <cuda_fp16.h>
#include <cstdint>

#define BATCH   16384
#define FEAT    512
#define NODES   4095
#define NPAD    4096
#define SPLIT   511            // nodes < SPLIT (levels 0-8) stored fp32

#define BM 128
#define BN 128
#define BKH 64                 // halves per k-stage (128B rows)
#define NKSTAGE (FEAT / BKH)   // 8
#define PSTAGES 3              // cp.async pipeline depth

// smem: A stages [0,48K), B stages [48K,96K), bias 96K, scale 96K+512
#define SMA(s)   ((s) * 16384)
#define SMB(s)   (49152 + (s) * 16384)
#define SM_BIAS  98304
#define SM_SCALE 98816
#define SM_TOTAL 99328

__device__ float  g_P32[(size_t)512 * BATCH];        // levels 0-8  (nodes 0..510)
__device__ __half g_P16[(size_t)NPAD * BATCH];       // levels 9-11 (nodes 511..4094)
__device__ __half g_Xh[(size_t)BATCH * FEAT];
__device__ __half g_Wh[(size_t)NPAD * FEAT];         // row 4095 zeroed

__device__ __forceinline__ float fast_sigmoid(float x) {
    return 1.0f / (1.0f + __expf(-x));
}
__device__ __forceinline__ uint32_t smem_u32(const void* p) {
    return (uint32_t)__cvta_generic_to_shared(p);
}
__device__ __forceinline__ void cp16(uint32_t dst, const void* src) {
    asm volatile("cp.async.cg.shared.global [%0], [%1], 16;" :: "r"(dst), "l"(src));
}
__device__ __forceinline__ void cp_commit() {
    asm volatile("cp.async.commit_group;" ::: "memory");
}
__device__ __forceinline__ void cp_wait1() {
    asm volatile("cp.async.wait_group 1;" ::: "memory");
}
__device__ __forceinline__ void ldsm4(uint32_t& r0, uint32_t& r1, uint32_t& r2,
                                      uint32_t& r3, uint32_t a) {
    asm volatile("ldmatrix.sync.aligned.m8n8.x4.shared.b16 {%0,%1,%2,%3}, [%4];"
                 : "=r"(r0), "=r"(r1), "=r"(r2), "=r"(r3) : "r"(a));
}
__device__ __forceinline__ void mma_f16(float* c, const uint32_t* a, const uint32_t* b) {
    asm volatile(
        "mma.sync.aligned.m16n8k16.row.col.f32.f16.f16.f32 "
        "{%0,%1,%2,%3}, {%4,%5,%6,%7}, {%8,%9}, {%0,%1,%2,%3};"
        : "+f"(c[0]), "+f"(c[1]), "+f"(c[2]), "+f"(c[3])
        : "r"(a[0]), "r"(a[1]), "r"(a[2]), "r"(a[3]), "r"(b[0]), "r"(b[1]));
}

// ---------------------------------------------------------------------------
// Convert kernels: fp32 -> fp16 copies of X and W (W padded to 4096 rows)
// ---------------------------------------------------------------------------
__global__ __launch_bounds__(256)
void convX(const float* __restrict__ X)
{
    size_t i = (size_t)blockIdx.x * 256 + threadIdx.x;   // float4 index
    float4 v = ((const float4*)X)[i];
    __half2* d = (__half2*)g_Xh;
    d[2 * i]     = __floats2half2_rn(v.x, v.y);
    d[2 * i + 1] = __floats2half2_rn(v.z, v.w);
}
__global__ __launch_bounds__(256)
void convW(const float* __restrict__ W)
{
    size_t i = (size_t)blockIdx.x * 256 + threadIdx.x;   // float4 index
    __half2* d = (__half2*)g_Wh;
    if (i < (size_t)NODES * FEAT / 4) {
        float4 v = ((const float4*)W)[i];
        d[2 * i]     = __floats2half2_rn(v.x, v.y);
        d[2 * i + 1] = __floats2half2_rn(v.z, v.w);
    } else {
        d[2 * i]     = __floats2half2_rn(0.f, 0.f);
        d[2 * i + 1] = __floats2half2_rn(0.f, 0.f);
    }
}

// ---------------------------------------------------------------------------
// Kernel 1: fp16 mma.sync GEMM (cp.async + ldmatrix) -> hybrid P
// ---------------------------------------------------------------------------
__global__ __launch_bounds__(256, 2)
void gemm_mma(const float* __restrict__ bias, const float* __restrict__ scale)
{
    extern __shared__ char smem[];
    const uint32_t sbase = smem_u32(smem);

    const int tid  = threadIdx.x;
    const int lane = tid & 31;
    const int wid  = tid >> 5;
    const int warpM = wid & 1;          // 2 x 64 rows
    const int warpN = wid >> 1;         // 4 x 32 cols
    const int m0 = blockIdx.y * BM;
    const int n0 = blockIdx.x * BN;

    float* sb = (float*)(smem + SM_BIAS);
    float* ss = (float*)(smem + SM_SCALE);
    if (tid < BN) {
        int nn = n0 + tid;
        bool v = nn < NODES;
        sb[tid] = v ? bias[nn] : 0.f;
        ss[tid] = v ? scale[nn] : 1.f;
    }

    auto issue_stage = [&](int kt) {
        const int s = kt % PSTAGES;
        const int kb = kt * BKH;
        #pragma unroll
        for (int i = 0; i < 4; ++i) {
            int c = tid + i * 256;                     // 0..1023
            int row = c >> 3, chk = c & 7;
            uint32_t coff = (uint32_t)(chk * 16) ^ ((row & 7) << 4);
            cp16(sbase + SMA(s) + row * 128 + coff,
                 g_Xh + (size_t)(m0 + row) * FEAT + kb + chk * 8);
        }
        #pragma unroll
        for (int i = 0; i < 4; ++i) {
            int c = tid + i * 256;
            int row = c >> 3, chk = c & 7;
            uint32_t coff = (uint32_t)(chk * 16) ^ ((row & 7) << 4);
            cp16(sbase + SMB(s) + row * 128 + coff,
                 g_Wh + (size_t)(n0 + row) * FEAT + kb + chk * 8);
        }
        cp_commit();
    };

    float acc[4][4][4];
    #pragma unroll
    for (int f = 0; f < 4; f++)
        #pragma unroll
        for (int g = 0; g < 4; g++)
            #pragma unroll
            for (int j = 0; j < 4; j++)
                acc[f][g][j] = 0.f;

    issue_stage(0);
    issue_stage(1);

    const int q  = lane >> 3;           // 0..3
    const int lr = lane & 7;            // 0..7

    for (int kt = 0; kt < NKSTAGE; ++kt) {
        cp_wait1();
        __syncthreads();
        if (kt + 2 < NKSTAGE) issue_stage(kt + 2);
        else cp_commit();

        const uint32_t abase = sbase + SMA(kt % PSTAGES);
        const uint32_t bbase = sbase + SMB(kt % PSTAGES);

        #pragma unroll
        for (int g = 0; g < 4; ++g) {   // k16 groups within BK=64
            uint32_t af[4][4];
            #pragma unroll
            for (int t = 0; t < 4; ++t) {
                int trow = warpM * 64 + t * 16 + lr + (q & 1) * 8;
                uint32_t kbyte = (uint32_t)(g * 32 + (q >> 1) * 16);
                uint32_t addr = abase + trow * 128 + (kbyte ^ ((trow & 7) << 4));
                ldsm4(af[t][0], af[t][1], af[t][2], af[t][3], addr);
            }
            uint32_t bf[2][4];
            #pragma unroll
            for (int t = 0; t < 2; ++t) {
                int nrow = warpN * 32 + t * 16 + lr + (q >> 1) * 8;
                uint32_t kbyte = (uint32_t)(g * 32 + (q & 1) * 16);
                uint32_t addr = bbase + nrow * 128 + (kbyte ^ ((nrow & 7) << 4));
                ldsm4(bf[t][0], bf[t][1], bf[t][2], bf[t][3], addr);
            }
            #pragma unroll
            for (int f = 0; f < 4; ++f)
                #pragma unroll
                for (int gg = 0; gg < 4; ++gg) {
                    uint32_t bb[2] = { bf[gg >> 1][(gg & 1) * 2],
                                       bf[gg >> 1][(gg & 1) * 2 + 1] };
                    mma_f16(acc[f][gg], af[f], bb);
                }
        }
        __syncthreads();
    }

    // Epilogue: C frag m16n8 -> hybrid P (fp32 for node<SPLIT, fp16 otherwise)
    const int rbase = m0 + warpM * 64 + (lane >> 2);
    #pragma unroll
    for (int f = 0; f < 4; ++f) {
        #pragma unroll
        for (int g = 0; g < 4; ++g) {
            const int cidx = warpN * 32 + g * 8 + (lane & 3) * 2;
            const int m = rbase + f * 16;
            #pragma unroll
            for (int j = 0; j < 4; ++j) {
                const int col = cidx + (j & 1);
                const int mm  = m + ((j >> 1) ? 8 : 0);
                const int node = n0 + col;
                float p = fast_sigmoid((acc[f][g][j] + sb[col]) * ss[col]);
                if (node < SPLIT)
                    g_P32[(size_t)node * BATCH + mm] = p;
                else
                    g_P16[(size_t)node * BATCH + mm] = __float2half_rn(p);
            }
        }
    }
}

// ---------------------------------------------------------------------------
// Kernel 2: leaf-group tree walk. 512 thr = 32 rows x 16 segs of 32 groups.
// Upper 9 levels from fp32 P, bottom 3 levels from fp16 P.
// ---------------------------------------------------------------------------
__global__ __launch_bounds__(512)
void tree_kernel(const float* __restrict__ leaves, float* __restrict__ out)
{
    __shared__ float sl[4096];
    __shared__ float part[16][33];
    const int tid = threadIdx.x;

    for (int i = tid; i < 4096; i += 512)
        sl[i] = fast_sigmoid(leaves[i]);
    __syncthreads();

    const int rlane = tid & 31;
    const int seg   = tid >> 5;              // 0..15
    const int r     = blockIdx.x * 32 + rlane;
    const float*  __restrict__ PT  = g_P32;
    const __half* __restrict__ PH  = g_P16;

    float acc = 0.f;
    const int g0 = seg * 32;
    #pragma unroll 2
    for (int gi = 0; gi < 32; ++gi) {
        const int g = g0 + gi;
        // levels 0-8 (fp32)
        float pref = 1.f;
        #pragma unroll
        for (int d = 0; d < 9; ++d) {
            int idx = (1 << d) - 1 + (g >> (9 - d));
            float p = PT[(size_t)idx * BATCH + r];
            int b = (g >> (8 - d)) & 1;
            pref = b ? (pref - pref * p) : (pref * p);
        }
        // levels 9-11 (fp16)
        float p9  = __half2float(PH[(size_t)(511  + g)     * BATCH + r]);
        float pa0 = __half2float(PH[(size_t)(1023 + 2 * g) * BATCH + r]);
        float pa1 = __half2float(PH[(size_t)(1024 + 2 * g) * BATCH + r]);
        float pb0 = __half2float(PH[(size_t)(2047 + 4 * g) * BATCH + r]);
        float pb1 = __half2float(PH[(size_t)(2048 + 4 * g) * BATCH + r]);
        float pb2 = __half2float(PH[(size_t)(2049 + 4 * g) * BATCH + r]);
        float pb3 = __half2float(PH[(size_t)(2050 + 4 * g) * BATCH + r]);

        float u0 = pref * p9,  u1 = pref - u0;
        float v0 = u0 * pa0,   v1 = u0 - v0;
        float v2 = u1 * pa1,   v3 = u1 - v2;
        float w0 = v0 * pb0,   w1 = v0 - w0;
        float w2 = v1 * pb1,   w3 = v1 - w2;
        float w4 = v2 * pb2,   w5 = v2 - w4;
        float w6 = v3 * pb3,   w7 = v3 - w6;

        const float* s8 = &sl[g * 8];
        acc += s8[0] * w0 + s8[1] * w1 + s8[2] * w2 + s8[3] * w3
             + s8[4] * w4 + s8[5] * w5 + s8[6] * w6 + s8[7] * w7;
    }
    part[seg][rlane] = acc;
    __syncthreads();
    if (tid < 32) {
        float t = 0.f;
        #pragma unroll
        for (int s2 = 0; s2 < 16; ++s2) t += part[s2][tid];
        out[blockIdx.x * 32 + tid] = t;
    }
}

// ---------------------------------------------------------------------------
extern "C" void kernel_launch(void* const* d_in, const int* in_sizes, int n_in,
                              void* d_out, int out_size)
{
    const float* X      = (const float*)d_in[0];  // [16384, 512]
    const float* W      = (const float*)d_in[1];  // [4095, 512]
    const float* b      = (const float*)d_in[2];  // [4095]
    const float* s      = (const float*)d_in[3];  // [4095]
    const float* leaves = (const float*)d_in[4];  // [4096]
    float* out = (float*)d_out;                   // [16384]

    static bool attr_set = false;
    if (!attr_set) {
        cudaFuncSetAttribute(gemm_mma, cudaFuncAttributeMaxDynamicSharedMemorySize,
                             SM_TOTAL);
        attr_set = true;
    }

    convX<<<BATCH * FEAT / 4 / 256, 256>>>(X);
    convW<<<NPAD * FEAT / 4 / 256, 256>>>(W);
    dim3 g1(NPAD / BN, BATCH / BM);               // (32, 128)
    gemm_mma<<<g1, 256, SM_TOTAL>>>(b, s);
    tree_kernel<<<512, 512>>>(leaves, out);
}